// round 4
// baseline (speedup 1.0000x reference)
#include <cuda_runtime.h>
#include <cstdint>

#define NMAX  100000
#define EMAX  1600000
#define BINSMAX (NMAX * 2)

// ---------------- scratch (device globals; no runtime allocation) ----------------
__device__ float d_S[(size_t)NMAX * 256];    // per-node, per-relation mean-aggregated features
__device__ float d_H[(size_t)NMAX * 128];    // layer-1 hidden activations
__device__ int   d_cnt[BINSMAX];             // (dst,rel) histogram
__device__ int   d_off[BINSMAX + 1];         // CSR offsets
__device__ int   d_cur[BINSMAX];             // scatter cursors
__device__ int   d_csr[EMAX];                // src index per CSR slot
__device__ float d_W1[384 * 128];            // [W1_root; W1_rel0; W1_rel1]
__device__ float d_W2[384 * 64];             // [W2_root; W2_rel0; W2_rel1]
__device__ int   d_is64;                     // 1 if edge buffers are int64
__device__ int   d_part[64];                 // per-block scan partials

// ---------------- packed f32x2 helpers (sm_103a: fma.rn.f32x2) ----------------
__device__ __forceinline__ unsigned long long pack2(float x) {
    unsigned long long r;
    asm("mov.b64 %0, {%1, %1};" : "=l"(r) : "f"(x));
    return r;
}
__device__ __forceinline__ void ffma2(unsigned long long& d,
                                      unsigned long long a, unsigned long long b) {
    asm("fma.rn.f32x2 %0, %1, %2, %0;" : "+l"(d) : "l"(a), "l"(b));
}
__device__ __forceinline__ float2 unpack2(unsigned long long v) {
    float2 f;
    asm("mov.b64 {%0, %1}, %2;" : "=f"(f.x), "=f"(f.y) : "l"(v));
    return f;
}

// ---------------- dtype probe: are edge indices int64 or int32? ----------------
__global__ void detect_dtype_kernel(const void* ei, int N) {
    const long long* p = (const long long*)ei;
    int ok = 1;
    for (int i = 0; i < 32; i++) {
        long long v = p[i];
        if (v < 0 || v >= (long long)N) { ok = 0; break; }
    }
    d_is64 = ok;
}

__device__ __forceinline__ int load_idx(const void* p, size_t i, int is64, int N) {
    long long v = is64 ? ((const long long*)p)[i] : (long long)((const int*)p)[i];
    if (v < 0) v = 0;
    if (v >= N) v = N - 1;
    return (int)v;
}

// ---------------- CSR build ----------------
__global__ void zero_cnt_kernel(int bins) {
    int i = blockIdx.x * blockDim.x + threadIdx.x;
    if (i < bins) d_cnt[i] = 0;
}

__global__ void hist_kernel(const void* __restrict__ ei,
                            const void* __restrict__ et, int E, int N) {
    int e = blockIdx.x * blockDim.x + threadIdx.x;
    if (e >= E) return;
    int is64 = d_is64;
    int dst = load_idx(ei, (size_t)E + e, is64, N);
    int rel = load_idx(et, e, is64, 2);
    atomicAdd(&d_cnt[dst * 2 + rel], 1);
}

// ---------------- multi-block scan ----------------
#define SCAN_T 256
#define SCAN_PER 16
#define SCAN_TILE (SCAN_T * SCAN_PER)   // 4096

__global__ void block_sum_kernel(int n) {
    int b = blockIdx.x;
    int tid = threadIdx.x, lane = tid & 31, wid = tid >> 5;
    int i0 = b * SCAN_TILE + tid * SCAN_PER;
    int s = 0;
#pragma unroll
    for (int p = 0; p < SCAN_PER; p++) {
        int i = i0 + p;
        if (i < n) s += d_cnt[i];
    }
#pragma unroll
    for (int d = 16; d > 0; d >>= 1) s += __shfl_xor_sync(0xffffffffu, s, d);
    __shared__ int ws[8];
    if (lane == 0) ws[wid] = s;
    __syncthreads();
    if (tid == 0) {
        int t = 0;
#pragma unroll
        for (int w = 0; w < 8; w++) t += ws[w];
        d_part[b] = t;
    }
}

__global__ void scan_part_kernel(int nparts, int n) {
    if (threadIdx.x == 0) {
        int acc = 0;
        for (int i = 0; i < nparts; i++) {
            int v = d_part[i];
            d_part[i] = acc;
            acc += v;
        }
        d_off[n] = acc;
    }
}

__global__ void block_scan_kernel(int n) {
    int b = blockIdx.x;
    int tid = threadIdx.x, lane = tid & 31, wid = tid >> 5;
    int base = d_part[b];
    int i0 = b * SCAN_TILE + tid * SCAN_PER;
    int vals[SCAN_PER];
    int sum = 0;
#pragma unroll
    for (int p = 0; p < SCAN_PER; p++) {
        int i = i0 + p;
        int v = (i < n) ? d_cnt[i] : 0;
        vals[p] = sum;
        sum += v;
    }
    int incl = sum;
#pragma unroll
    for (int d = 1; d < 32; d <<= 1) {
        int t = __shfl_up_sync(0xffffffffu, incl, d);
        if (lane >= d) incl += t;
    }
    __shared__ int ws[8];
    if (lane == 31) ws[wid] = incl;
    __syncthreads();
    if (wid == 0 && lane < 8) {
        int w = ws[lane];
#pragma unroll
        for (int d = 1; d < 8; d <<= 1) {
            int t = __shfl_up_sync(0xffu, w, d);
            if (lane >= d) w += t;
        }
        ws[lane] = w;
    }
    __syncthreads();
    int off = base + ((wid > 0) ? ws[wid - 1] : 0) + (incl - sum);
#pragma unroll
    for (int p = 0; p < SCAN_PER; p++) {
        int i = i0 + p;
        if (i < n) {
            int o = off + vals[p];
            d_off[i] = o;
            d_cur[i] = o;
        }
    }
}

__global__ void scatter_kernel(const void* __restrict__ ei,
                               const void* __restrict__ et, int E, int N) {
    int e = blockIdx.x * blockDim.x + threadIdx.x;
    if (e >= E) return;
    int is64 = d_is64;
    int src = load_idx(ei, e, is64, N);
    int dst = load_idx(ei, (size_t)E + e, is64, N);
    int rel = load_idx(et, e, is64, 2);
    int pos = atomicAdd(&d_cur[dst * 2 + rel], 1);
    if (pos < EMAX) d_csr[pos] = src;
}

// ---------------- weight concat ----------------
__global__ void build_wcat_kernel(const float* __restrict__ root,
                                  const float* __restrict__ rel,
                                  float* __restrict__ W, int nc) {
    int i = blockIdx.x * blockDim.x + threadIdx.x;
    if (i >= 384 * nc) return;
    int r = i / nc;
    W[i] = (r < 128) ? root[i] : rel[i - 128 * nc];
}

// ---------------- per-(dst,rel) mean aggregation: one warp per segment ----------------
__global__ void aggregate_kernel(const float* __restrict__ feat, int bins) {
    int w = (blockIdx.x * blockDim.x + threadIdx.x) >> 5;
    int lane = threadIdx.x & 31;
    if (w >= bins) return;
    int beg = d_off[w], end = d_off[w + 1];
    float4 acc = make_float4(0.f, 0.f, 0.f, 0.f);
    int e = beg;
    for (; e + 2 <= end; e += 2) {
        int s0 = d_csr[e], s1 = d_csr[e + 1];
        float4 v0 = __ldg((const float4*)(feat + (size_t)s0 * 128) + lane);
        float4 v1 = __ldg((const float4*)(feat + (size_t)s1 * 128) + lane);
        acc.x += v0.x + v1.x;
        acc.y += v0.y + v1.y;
        acc.z += v0.z + v1.z;
        acc.w += v0.w + v1.w;
    }
    if (e < end) {
        int s0 = d_csr[e];
        float4 v0 = __ldg((const float4*)(feat + (size_t)s0 * 128) + lane);
        acc.x += v0.x;
        acc.y += v0.y;
        acc.z += v0.z;
        acc.w += v0.w;
    }
    int c = end - beg;
    float sc = 1.0f / (float)max(c, 1);
    acc.x *= sc; acc.y *= sc; acc.z *= sc; acc.w *= sc;
    ((float4*)(d_S + (size_t)w * 128))[lane] = acc;
}

// ---------------- fused GEMM with packed f32x2 FMA ----------------
// C[M,BN] = [A0 | A1] (M x 384) @ W (384 x BN) + bias, opt ReLU
// A0: ld 128 (k in [0,128)); A1: ld 256 (k in [128,384))
template <int BN, bool RELU>
__global__ void gemm_fused(const float* __restrict__ A0, const float* __restrict__ A1,
                           const float* __restrict__ W, const float* __restrict__ bias,
                           float* __restrict__ C, int M) {
    constexpr int BM = 128, BK = 16;
    constexpr int TX = BN / 8, TY = 16, T = TX * TY;
    __shared__ float As[BK][BM + 4];
    __shared__ float Bs[BK][BN];
    int tid = threadIdx.x;
    int tx = tid % TX, ty = tid / TX;
    int rowBase = blockIdx.x * BM;

    // accumulators: 8 rows x 4 packed float2 pairs (cols)
    unsigned long long accP[8][4];
#pragma unroll
    for (int i = 0; i < 8; i++)
#pragma unroll
        for (int j = 0; j < 4; j++) accP[i][j] = 0ull;

    for (int k0 = 0; k0 < 384; k0 += BK) {
        const float* Ab;
        int lda;
        if (k0 < 128) { Ab = A0 + k0; lda = 128; }
        else          { Ab = A1 + (k0 - 128); lda = 256; }
#pragma unroll
        for (int t = 0; t < (BM * BK / 4) / T; t++) {
            int idx = tid + t * T;
            int m = idx >> 2, q = idx & 3;
            int gm = rowBase + m;
            float4 v = make_float4(0.f, 0.f, 0.f, 0.f);
            if (gm < M) v = *(const float4*)(Ab + (size_t)gm * lda + q * 4);
            As[q * 4 + 0][m] = v.x;
            As[q * 4 + 1][m] = v.y;
            As[q * 4 + 2][m] = v.z;
            As[q * 4 + 3][m] = v.w;
        }
#pragma unroll
        for (int t = 0; t < (BK * BN / 4) / T; t++) {
            int idx = tid + t * T;
            int k = idx / (BN / 4), nq = idx % (BN / 4);
            float4 v = *(const float4*)(W + (size_t)(k0 + k) * BN + nq * 4);
            *(float4*)&Bs[k][nq * 4] = v;
        }
        __syncthreads();
#pragma unroll
        for (int kk = 0; kk < BK; kk++) {
            float a[8];
            *(float4*)&a[0] = *(const float4*)&As[kk][ty * 8];
            *(float4*)&a[4] = *(const float4*)&As[kk][ty * 8 + 4];
            unsigned long long b2[4];
#pragma unroll
            for (int j2 = 0; j2 < 4; j2++)
                b2[j2] = *(const unsigned long long*)&Bs[kk][tx * 8 + j2 * 2];
#pragma unroll
            for (int i = 0; i < 8; i++) {
                unsigned long long a2 = pack2(a[i]);
#pragma unroll
                for (int j2 = 0; j2 < 4; j2++) ffma2(accP[i][j2], a2, b2[j2]);
            }
        }
        __syncthreads();
    }

    float bv[8];
#pragma unroll
    for (int j = 0; j < 8; j++) bv[j] = bias[tx * 8 + j];
#pragma unroll
    for (int i = 0; i < 8; i++) {
        int row = rowBase + ty * 8 + i;
        if (row < M) {
            float o[8];
#pragma unroll
            for (int j2 = 0; j2 < 4; j2++) {
                float2 v = unpack2(accP[i][j2]);
                o[j2 * 2 + 0] = v.x + bv[j2 * 2 + 0];
                o[j2 * 2 + 1] = v.y + bv[j2 * 2 + 1];
            }
            if (RELU) {
#pragma unroll
                for (int j = 0; j < 8; j++) o[j] = fmaxf(o[j], 0.f);
            }
            *(float4*)&C[(size_t)row * BN + tx * 8]     = *(float4*)&o[0];
            *(float4*)&C[(size_t)row * BN + tx * 8 + 4] = *(float4*)&o[4];
        }
    }
}

// ---------------- row-wise L2 normalize (in place), 64 cols ----------------
__global__ void l2norm_kernel(float* __restrict__ out, int M) {
    int r = blockIdx.x * blockDim.x + threadIdx.x;
    if (r >= M) return;
    float4* p = (float4*)(out + (size_t)r * 64);
    float4 v[16];
    float s = 0.f;
#pragma unroll
    for (int i = 0; i < 16; i++) {
        v[i] = p[i];
        s += v[i].x * v[i].x + v[i].y * v[i].y + v[i].z * v[i].z + v[i].w * v[i].w;
    }
    float nr = sqrtf(s);
    float sc = 1.0f / fmaxf(nr, 1e-12f);
#pragma unroll
    for (int i = 0; i < 16; i++) {
        v[i].x *= sc; v[i].y *= sc; v[i].z *= sc; v[i].w *= sc;
        p[i] = v[i];
    }
}

// ---------------- launch ----------------
extern "C" void kernel_launch(void* const* d_in, const int* in_sizes, int n_in,
                              void* d_out, int out_size) {
    const float* x       = (const float*)d_in[0];
    const void*  ei      = d_in[1];
    const void*  et      = d_in[2];
    const float* W1_rel  = (const float*)d_in[3];
    const float* W1_root = (const float*)d_in[4];
    const float* b1      = (const float*)d_in[5];
    const float* W2_rel  = (const float*)d_in[6];
    const float* W2_root = (const float*)d_in[7];
    const float* b2      = (const float*)d_in[8];
    float* out = (float*)d_out;

    int M = in_sizes[0] / 128;   // 100000 nodes
    int E = in_sizes[2];         // 1600000 edges
    int bins = M * 2;
    int nparts = (bins + SCAN_TILE - 1) / SCAN_TILE;

    float *S, *H, *W1c, *W2c;
    cudaGetSymbolAddress((void**)&S,   d_S);
    cudaGetSymbolAddress((void**)&H,   d_H);
    cudaGetSymbolAddress((void**)&W1c, d_W1);
    cudaGetSymbolAddress((void**)&W2c, d_W2);

    // probe edge-index dtype, then build CSR
    detect_dtype_kernel<<<1, 1>>>(ei, M);
    zero_cnt_kernel<<<(bins + 255) / 256, 256>>>(bins);
    hist_kernel<<<(E + 255) / 256, 256>>>(ei, et, E, M);
    block_sum_kernel<<<nparts, SCAN_T>>>(bins);
    scan_part_kernel<<<1, 32>>>(nparts, bins);
    block_scan_kernel<<<nparts, SCAN_T>>>(bins);
    scatter_kernel<<<(E + 255) / 256, 256>>>(ei, et, E, M);

    // weight concatenation
    build_wcat_kernel<<<(384 * 128 + 255) / 256, 256>>>(W1_root, W1_rel, W1c, 128);
    build_wcat_kernel<<<(384 * 64 + 255) / 256, 256>>>(W2_root, W2_rel, W2c, 64);

    // layer 1: aggregate x -> S, fused GEMM (+bias+ReLU) -> H
    aggregate_kernel<<<(bins * 32 + 255) / 256, 256>>>(x, bins);
    gemm_fused<128, true><<<(M + 127) / 128, 256>>>(x, S, W1c, b1, H, M);

    // layer 2: aggregate H -> S, fused GEMM (+bias) -> out
    aggregate_kernel<<<(bins * 32 + 255) / 256, 256>>>(H, bins);
    gemm_fused<64, false><<<(M + 127) / 128, 128>>>(H, S, W2c, b2, out, M);

    // final row-wise L2 normalize in place
    l2norm_kernel<<<(M + 255) / 256, 256>>>(out, M);
}

// round 8
// speedup vs baseline: 1.9541x; 1.9541x over previous
#include <cuda_runtime.h>
#include <cuda_bf16.h>
#include <cstdint>

#define NMAX  100000
#define EMAX  1600000
#define BINSMAX (NMAX * 2)
#define KA    384            // concatenated K dim: [root(128) | rel0(128) | rel1(128)]

// ---------------- scratch (device globals; no runtime allocation) ----------------
__device__ __align__(16) float          d_H[(size_t)NMAX * 128];   // layer-1 hidden (fp32)
__device__ __align__(16) __nv_bfloat16  d_A1h[(size_t)NMAX * KA];  // layer-1 A hi (reused as fp32 O for layer-2 out)
__device__ __align__(16) __nv_bfloat16  d_A1l[(size_t)NMAX * KA];  // layer-1 A lo
__device__ __align__(16) __nv_bfloat16  d_A2h[(size_t)NMAX * KA];  // layer-2 A hi
__device__ __align__(16) __nv_bfloat16  d_A2l[(size_t)NMAX * KA];  // layer-2 A lo
__device__ __align__(16) __nv_bfloat16  d_Wt1h[128 * KA];          // W1^T hi [N=128][K=384]
__device__ __align__(16) __nv_bfloat16  d_Wt1l[128 * KA];
__device__ __align__(16) __nv_bfloat16  d_Wt2h[64 * KA];           // W2^T hi [N=64][K=384]
__device__ __align__(16) __nv_bfloat16  d_Wt2l[64 * KA];
__device__ int   d_cnt[BINSMAX];
__device__ int   d_off[BINSMAX + 1];
__device__ int   d_cur[BINSMAX];
__device__ int   d_csr[EMAX];
__device__ int   d_is64;
__device__ int   d_part[64];

// ---------------- small helpers ----------------
__device__ __forceinline__ void bf_split(float v, __nv_bfloat16& h, __nv_bfloat16& l) {
    h = __float2bfloat16_rn(v);
    l = __float2bfloat16_rn(v - __bfloat162float(h));
}
__device__ __forceinline__ unsigned pack_bf2(__nv_bfloat16 a, __nv_bfloat16 b) {
    return (unsigned)__bfloat16_as_ushort(a) | ((unsigned)__bfloat16_as_ushort(b) << 16);
}
__device__ __forceinline__ uint32_t smem_u32(const void* p) {
    uint32_t a;
    asm("{ .reg .u64 t; cvta.to.shared.u64 t, %1; cvt.u32.u64 %0, t; }" : "=r"(a) : "l"(p));
    return a;
}
__device__ __forceinline__ void ldsm_x4(uint32_t& r0, uint32_t& r1, uint32_t& r2, uint32_t& r3,
                                        uint32_t addr) {
    asm volatile("ldmatrix.sync.aligned.m8n8.x4.shared.b16 {%0,%1,%2,%3}, [%4];"
                 : "=r"(r0), "=r"(r1), "=r"(r2), "=r"(r3) : "r"(addr));
}
__device__ __forceinline__ void mma_bf16(float* c,
                                         uint32_t a0, uint32_t a1, uint32_t a2, uint32_t a3,
                                         uint32_t b0, uint32_t b1) {
    asm volatile("mma.sync.aligned.m16n8k16.row.col.f32.bf16.bf16.f32 "
                 "{%0,%1,%2,%3}, {%4,%5,%6,%7}, {%8,%9}, {%0,%1,%2,%3};"
                 : "+f"(c[0]), "+f"(c[1]), "+f"(c[2]), "+f"(c[3])
                 : "r"(a0), "r"(a1), "r"(a2), "r"(a3), "r"(b0), "r"(b1));
}

// ---------------- dtype probe ----------------
__global__ void detect_dtype_kernel(const void* ei, int N) {
    const long long* p = (const long long*)ei;
    int ok = 1;
    for (int i = 0; i < 32; i++) {
        long long v = p[i];
        if (v < 0 || v >= (long long)N) { ok = 0; break; }
    }
    d_is64 = ok;
}
__device__ __forceinline__ int load_idx(const void* p, size_t i, int is64, int N) {
    long long v = is64 ? ((const long long*)p)[i] : (long long)((const int*)p)[i];
    if (v < 0) v = 0;
    if (v >= N) v = N - 1;
    return (int)v;
}

// ---------------- CSR build ----------------
__global__ void zero_cnt_kernel(int bins) {
    int i = blockIdx.x * blockDim.x + threadIdx.x;
    if (i < bins) d_cnt[i] = 0;
}
__global__ void hist_kernel(const void* __restrict__ ei, const void* __restrict__ et,
                            int E, int N) {
    int e = blockIdx.x * blockDim.x + threadIdx.x;
    if (e >= E) return;
    int is64 = d_is64;
    int dst = load_idx(ei, (size_t)E + e, is64, N);
    int rel = load_idx(et, e, is64, 2);
    atomicAdd(&d_cnt[dst * 2 + rel], 1);
}

#define SCAN_T 256
#define SCAN_PER 16
#define SCAN_TILE (SCAN_T * SCAN_PER)

__global__ void block_sum_kernel(int n) {
    int b = blockIdx.x;
    int tid = threadIdx.x, lane = tid & 31, wid = tid >> 5;
    int i0 = b * SCAN_TILE + tid * SCAN_PER;
    int s = 0;
#pragma unroll
    for (int p = 0; p < SCAN_PER; p++) {
        int i = i0 + p;
        if (i < n) s += d_cnt[i];
    }
#pragma unroll
    for (int d = 16; d > 0; d >>= 1) s += __shfl_xor_sync(0xffffffffu, s, d);
    __shared__ int ws[8];
    if (lane == 0) ws[wid] = s;
    __syncthreads();
    if (tid == 0) {
        int t = 0;
#pragma unroll
        for (int w = 0; w < 8; w++) t += ws[w];
        d_part[b] = t;
    }
}
__global__ void scan_part_kernel(int nparts, int n) {
    if (threadIdx.x == 0) {
        int acc = 0;
        for (int i = 0; i < nparts; i++) {
            int v = d_part[i];
            d_part[i] = acc;
            acc += v;
        }
        d_off[n] = acc;
    }
}
__global__ void block_scan_kernel(int n) {
    int b = blockIdx.x;
    int tid = threadIdx.x, lane = tid & 31, wid = tid >> 5;
    int base = d_part[b];
    int i0 = b * SCAN_TILE + tid * SCAN_PER;
    int vals[SCAN_PER];
    int sum = 0;
#pragma unroll
    for (int p = 0; p < SCAN_PER; p++) {
        int i = i0 + p;
        int v = (i < n) ? d_cnt[i] : 0;
        vals[p] = sum;
        sum += v;
    }
    int incl = sum;
#pragma unroll
    for (int d = 1; d < 32; d <<= 1) {
        int t = __shfl_up_sync(0xffffffffu, incl, d);
        if (lane >= d) incl += t;
    }
    __shared__ int ws[8];
    if (lane == 31) ws[wid] = incl;
    __syncthreads();
    if (wid == 0 && lane < 8) {
        int w = ws[lane];
#pragma unroll
        for (int d = 1; d < 8; d <<= 1) {
            int t = __shfl_up_sync(0xffu, w, d);
            if (lane >= d) w += t;
        }
        ws[lane] = w;
    }
    __syncthreads();
    int off = base + ((wid > 0) ? ws[wid - 1] : 0) + (incl - sum);
#pragma unroll
    for (int p = 0; p < SCAN_PER; p++) {
        int i = i0 + p;
        if (i < n) {
            int o = off + vals[p];
            d_off[i] = o;
            d_cur[i] = o;
        }
    }
}
__global__ void scatter_kernel(const void* __restrict__ ei, const void* __restrict__ et,
                               int E, int N) {
    int e = blockIdx.x * blockDim.x + threadIdx.x;
    if (e >= E) return;
    int is64 = d_is64;
    int src = load_idx(ei, e, is64, N);
    int dst = load_idx(ei, (size_t)E + e, is64, N);
    int rel = load_idx(et, e, is64, 2);
    int pos = atomicAdd(&d_cur[dst * 2 + rel], 1);
    if (pos < EMAX) d_csr[pos] = src;
}

// ---------------- weight transpose + split: Wt[n][k] hi/lo ----------------
__global__ void build_wt_kernel(const float* __restrict__ root, const float* __restrict__ rel,
                                __nv_bfloat16* __restrict__ Wh, __nv_bfloat16* __restrict__ Wl,
                                int N) {
    int i = blockIdx.x * blockDim.x + threadIdx.x;
    if (i >= N * KA) return;
    int n = i / KA, k = i % KA;
    float v = (k < 128) ? root[k * N + n] : rel[(size_t)(k - 128) * N + n];
    __nv_bfloat16 h, l;
    bf_split(v, h, l);
    Wh[(size_t)n * KA + k] = h;
    Wl[(size_t)n * KA + k] = l;
}

// ---------------- x converter: A cols 0..127 <- x (split) ----------------
__global__ void convert_x_kernel(const float* __restrict__ x,
                                 __nv_bfloat16* __restrict__ Ah, __nv_bfloat16* __restrict__ Al,
                                 int M) {
    int idx = blockIdx.x * blockDim.x + threadIdx.x;
    if (idx >= M * 32) return;
    int row = idx >> 5, q = idx & 31;
    float4 v = *(const float4*)(x + (size_t)row * 128 + q * 4);
    __nv_bfloat16 h0, l0, h1, l1, h2, l2, h3, l3;
    bf_split(v.x, h0, l0); bf_split(v.y, h1, l1);
    bf_split(v.z, h2, l2); bf_split(v.w, h3, l3);
    size_t o = (size_t)row * KA + q * 4;
    *(uint2*)(Ah + o) = make_uint2(pack_bf2(h0, h1), pack_bf2(h2, h3));
    *(uint2*)(Al + o) = make_uint2(pack_bf2(l0, l1), pack_bf2(l2, l3));
}

// ---------------- aggregation: one warp per (dst,rel); writes A cols 128+rel*128 ----------------
__global__ void aggregate_kernel(const float* __restrict__ feat,
                                 __nv_bfloat16* __restrict__ Ah, __nv_bfloat16* __restrict__ Al,
                                 int bins) {
    int w = (blockIdx.x * blockDim.x + threadIdx.x) >> 5;
    int lane = threadIdx.x & 31;
    if (w >= bins) return;
    int beg = d_off[w], end = d_off[w + 1];
    float4 acc = make_float4(0.f, 0.f, 0.f, 0.f);
    int e = beg;
    for (; e + 2 <= end; e += 2) {
        int s0 = d_csr[e], s1 = d_csr[e + 1];
        float4 v0 = __ldg((const float4*)(feat + (size_t)s0 * 128) + lane);
        float4 v1 = __ldg((const float4*)(feat + (size_t)s1 * 128) + lane);
        acc.x += v0.x + v1.x; acc.y += v0.y + v1.y;
        acc.z += v0.z + v1.z; acc.w += v0.w + v1.w;
    }
    if (e < end) {
        int s0 = d_csr[e];
        float4 v0 = __ldg((const float4*)(feat + (size_t)s0 * 128) + lane);
        acc.x += v0.x; acc.y += v0.y; acc.z += v0.z; acc.w += v0.w;
    }
    float sc = 1.0f / (float)max(end - beg, 1);
    acc.x *= sc; acc.y *= sc; acc.z *= sc; acc.w *= sc;
    int node = w >> 1, rel = w & 1;
    size_t o = (size_t)node * KA + 128 + rel * 128 + lane * 4;
    __nv_bfloat16 h0, l0, h1, l1, h2, l2, h3, l3;
    bf_split(acc.x, h0, l0); bf_split(acc.y, h1, l1);
    bf_split(acc.z, h2, l2); bf_split(acc.w, h3, l3);
    *(uint2*)(Ah + o) = make_uint2(pack_bf2(h0, h1), pack_bf2(h2, h3));
    *(uint2*)(Al + o) = make_uint2(pack_bf2(l0, l1), pack_bf2(l2, l3));
}

// ---------------- warp-MMA split-bf16 GEMM (ldmatrix + mma.sync, baseline PTX ISA) ----------------
// C[M,N] = A(Mx384 as hi+lo bf16) @ Wt^T  via  Ah*Bh + Ah*Bl + Al*Bh  (fp32 accum)
// CTA: 128 x N.  Warps: 4(m) x N/32(n), warp tile 32x32.  BK=32.
// smem rows padded to 80B (5x16B) -> conflict-free ldmatrix.
template <int N, bool LAYER1>
__global__ void __launch_bounds__(4 * N)
gemm_mma(const __nv_bfloat16* __restrict__ Ah, const __nv_bfloat16* __restrict__ Al,
         const __nv_bfloat16* __restrict__ Bh, const __nv_bfloat16* __restrict__ Bl,
         const float* __restrict__ bias,
         float* __restrict__ Hout, __nv_bfloat16* __restrict__ A2h, __nv_bfloat16* __restrict__ A2l,
         float* __restrict__ Out, int M) {
    constexpr int NT = 4 * N;            // threads: 512 (N=128) / 256 (N=64)
    constexpr int RS = 40;               // smem row stride in bf16 (80B)
    __shared__ __align__(16) uint16_t sAh[128 * RS];
    __shared__ __align__(16) uint16_t sAl[128 * RS];
    __shared__ __align__(16) uint16_t sBh[N * RS];
    __shared__ __align__(16) uint16_t sBl[N * RS];

    int tid = threadIdx.x, lane = tid & 31, wid = tid >> 5;
    int wm = wid & 3, wn = wid >> 2;     // warp tile: rows wm*32, cols wn*32
    int rowBase = blockIdx.x * 128;

    float acc[2][4][4];
#pragma unroll
    for (int i = 0; i < 2; i++)
#pragma unroll
        for (int j = 0; j < 4; j++)
#pragma unroll
            for (int q = 0; q < 4; q++) acc[i][j][q] = 0.f;

    // ldmatrix source addresses (byte offsets inside padded tiles)
    uint32_t aBase = smem_u32(sAh), alBase = smem_u32(sAl);
    uint32_t bBase = smem_u32(sBh), blBase = smem_u32(sBl);
    // A frag rows: wm*32 + mi*16 + (lane&15), k-half by lane>>4
    int arow = wm * 32 + (lane & 15);
    uint32_t aoff = (uint32_t)arow * (RS * 2) + (uint32_t)(lane >> 4) * 16;
    // B frag rows: wn*32 + nip*16 + (lane&7) + ((lane>>4)<<3), k-half by (lane>>3)&1
    int brow = wn * 32 + (lane & 7) + ((lane >> 4) << 3);
    uint32_t boff = (uint32_t)brow * (RS * 2) + (uint32_t)((lane >> 3) & 1) * 16;

    for (int k0 = 0; k0 < KA; k0 += 32) {
        // ---- load tiles ----
#pragma unroll
        for (int u = tid; u < 128 * 4; u += NT) {
            int r = u >> 2, c = u & 3;
            int gr = rowBase + r;
            uint4 vh = make_uint4(0, 0, 0, 0), vl = vh;
            if (gr < M) {
                size_t g = (size_t)gr * KA + k0 + c * 8;
                vh = *(const uint4*)(Ah + g);
                vl = *(const uint4*)(Al + g);
            }
            *(uint4*)(sAh + r * RS + c * 8) = vh;
            *(uint4*)(sAl + r * RS + c * 8) = vl;
        }
#pragma unroll
        for (int u = tid; u < N * 4; u += NT) {
            int r = u >> 2, c = u & 3;
            size_t g = (size_t)r * KA + k0 + c * 8;
            *(uint4*)(sBh + r * RS + c * 8) = *(const uint4*)(Bh + g);
            *(uint4*)(sBl + r * RS + c * 8) = *(const uint4*)(Bl + g);
        }
        __syncthreads();

        // ---- mma ----
#pragma unroll
        for (int ks = 0; ks < 32; ks += 16) {
            uint32_t ah[2][4], al[2][4];
#pragma unroll
            for (int mi = 0; mi < 2; mi++) {
                uint32_t o = aoff + (uint32_t)mi * 16 * (RS * 2) + (uint32_t)ks * 2;
                ldsm_x4(ah[mi][0], ah[mi][1], ah[mi][2], ah[mi][3], aBase + o);
                ldsm_x4(al[mi][0], al[mi][1], al[mi][2], al[mi][3], alBase + o);
            }
            uint32_t bh[4][2], bl[4][2];
#pragma unroll
            for (int nip = 0; nip < 2; nip++) {
                uint32_t o = boff + (uint32_t)nip * 16 * (RS * 2) + (uint32_t)ks * 2;
                uint32_t r0, r1, r2, r3;
                ldsm_x4(r0, r1, r2, r3, bBase + o);
                bh[nip * 2][0] = r0; bh[nip * 2][1] = r1;
                bh[nip * 2 + 1][0] = r2; bh[nip * 2 + 1][1] = r3;
                ldsm_x4(r0, r1, r2, r3, blBase + o);
                bl[nip * 2][0] = r0; bl[nip * 2][1] = r1;
                bl[nip * 2 + 1][0] = r2; bl[nip * 2 + 1][1] = r3;
            }
#pragma unroll
            for (int mi = 0; mi < 2; mi++)
#pragma unroll
                for (int ni = 0; ni < 4; ni++) {
                    mma_bf16(acc[mi][ni], ah[mi][0], ah[mi][1], ah[mi][2], ah[mi][3],
                             bh[ni][0], bh[ni][1]);
                    mma_bf16(acc[mi][ni], ah[mi][0], ah[mi][1], ah[mi][2], ah[mi][3],
                             bl[ni][0], bl[ni][1]);
                    mma_bf16(acc[mi][ni], al[mi][0], al[mi][1], al[mi][2], al[mi][3],
                             bh[ni][0], bh[ni][1]);
                }
        }
        __syncthreads();
    }

    // ---- epilogue ----
    // c-frag: c0,c1 -> (row lane/4, cols 2*(lane%4)+{0,1}); c2,c3 -> row+8
#pragma unroll
    for (int mi = 0; mi < 2; mi++) {
#pragma unroll
        for (int half = 0; half < 2; half++) {
            int r = rowBase + wm * 32 + mi * 16 + (lane >> 2) + half * 8;
            if (r >= M) continue;
#pragma unroll
            for (int ni = 0; ni < 4; ni++) {
                int cn = wn * 32 + ni * 8 + 2 * (lane & 3);
                float v0 = acc[mi][ni][half * 2 + 0] + __ldg(bias + cn);
                float v1 = acc[mi][ni][half * 2 + 1] + __ldg(bias + cn + 1);
                if (LAYER1) {
                    v0 = fmaxf(v0, 0.f);
                    v1 = fmaxf(v1, 0.f);
                    *(float2*)(Hout + (size_t)r * 128 + cn) = make_float2(v0, v1);
                    __nv_bfloat16 h0, l0, h1, l1;
                    bf_split(v0, h0, l0); bf_split(v1, h1, l1);
                    *(unsigned*)(A2h + (size_t)r * KA + cn) = pack_bf2(h0, h1);
                    *(unsigned*)(A2l + (size_t)r * KA + cn) = pack_bf2(l0, l1);
                } else {
                    *(float2*)(Out + (size_t)r * 64 + cn) = make_float2(v0, v1);
                }
            }
        }
    }
}

// ---------------- row-wise L2 normalize: out = normalize(O), 64 cols ----------------
__global__ void l2norm_kernel(const float* __restrict__ O, float* __restrict__ out, int M) {
    int r = blockIdx.x * blockDim.x + threadIdx.x;
    if (r >= M) return;
    const float4* p = (const float4*)(O + (size_t)r * 64);
    float4 v[16];
    float s = 0.f;
#pragma unroll
    for (int i = 0; i < 16; i++) {
        v[i] = p[i];
        s += v[i].x * v[i].x + v[i].y * v[i].y + v[i].z * v[i].z + v[i].w * v[i].w;
    }
    float sc = 1.0f / fmaxf(sqrtf(s), 1e-12f);
    float4* q = (float4*)(out + (size_t)r * 64);
#pragma unroll
    for (int i = 0; i < 16; i++) {
        v[i].x *= sc; v[i].y *= sc; v[i].z *= sc; v[i].w *= sc;
        q[i] = v[i];
    }
}

// ---------------- launch ----------------
extern "C" void kernel_launch(void* const* d_in, const int* in_sizes, int n_in,
                              void* d_out, int out_size) {
    const float* x       = (const float*)d_in[0];
    const void*  ei      = d_in[1];
    const void*  et      = d_in[2];
    const float* W1_rel  = (const float*)d_in[3];
    const float* W1_root = (const float*)d_in[4];
    const float* b1      = (const float*)d_in[5];
    const float* W2_rel  = (const float*)d_in[6];
    const float* W2_root = (const float*)d_in[7];
    const float* b2      = (const float*)d_in[8];
    float* out = (float*)d_out;

    int M = in_sizes[0] / 128;   // 100000
    int E = in_sizes[2];         // 1600000
    int bins = M * 2;
    int nparts = (bins + SCAN_TILE - 1) / SCAN_TILE;

    float *H;
    __nv_bfloat16 *A1h, *A1l, *A2h, *A2l, *Wt1h, *Wt1l, *Wt2h, *Wt2l;
    cudaGetSymbolAddress((void**)&H, d_H);
    cudaGetSymbolAddress((void**)&A1h, d_A1h);
    cudaGetSymbolAddress((void**)&A1l, d_A1l);
    cudaGetSymbolAddress((void**)&A2h, d_A2h);
    cudaGetSymbolAddress((void**)&A2l, d_A2l);
    cudaGetSymbolAddress((void**)&Wt1h, d_Wt1h);
    cudaGetSymbolAddress((void**)&Wt1l, d_Wt1l);
    cudaGetSymbolAddress((void**)&Wt2h, d_Wt2h);
    cudaGetSymbolAddress((void**)&Wt2l, d_Wt2l);
    float* O = (float*)A1h;      // reuse A1 hi buffer for layer-2 raw output

    // CSR build
    detect_dtype_kernel<<<1, 1>>>(ei, M);
    zero_cnt_kernel<<<(bins + 255) / 256, 256>>>(bins);
    hist_kernel<<<(E + 255) / 256, 256>>>(ei, et, E, M);
    block_sum_kernel<<<nparts, SCAN_T>>>(bins);
    scan_part_kernel<<<1, 32>>>(nparts, bins);
    block_scan_kernel<<<nparts, SCAN_T>>>(bins);
    scatter_kernel<<<(E + 255) / 256, 256>>>(ei, et, E, M);

    // weights: transpose + split
    build_wt_kernel<<<(128 * KA + 255) / 256, 256>>>(W1_root, W1_rel, Wt1h, Wt1l, 128);
    build_wt_kernel<<<(64 * KA + 255) / 256, 256>>>(W2_root, W2_rel, Wt2h, Wt2l, 64);

    // layer 1
    convert_x_kernel<<<(M * 32 + 255) / 256, 256>>>(x, A1h, A1l, M);
    aggregate_kernel<<<(bins * 32 + 255) / 256, 256>>>(x, A1h, A1l, bins);
    int grid = (M + 127) / 128;
    gemm_mma<128, true><<<grid, 512>>>(A1h, A1l, Wt1h, Wt1l, b1, H, A2h, A2l, nullptr, M);

    // layer 2
    aggregate_kernel<<<(bins * 32 + 255) / 256, 256>>>(H, A2h, A2l, bins);
    gemm_mma<64, false><<<grid, 256>>>(A2h, A2l, Wt2h, Wt2l, b2, nullptr, nullptr, nullptr, O, M);

    // final row-wise L2 normalize
    l2norm_kernel<<<(M + 255) / 256, 256>>>(O, out, M);
}